// round 4
// baseline (speedup 1.0000x reference)
#include <cuda_runtime.h>
#include <cuda_bf16.h>

#define Bz 256
#define Sz 512
#define Ez 100
#define Hz 64
#define Gz 256      // 4*H
#define Vz 50000
#define VP 50048    // padded vocab rows
#define NC 512      // 2 dirs * 256 gates

// Precomputed per-vocab input projections (+bias), layout [VP][NC]
__device__ float g_table[(size_t)VP * NC];   // ~102.5 MB
__device__ float g_hfin[2 * Bz * Hz];

// ---- f32x2 packed-math helpers ----
#define FMA2(acc, a, b) \
    asm("fma.rn.f32x2 %0, %1, %2, %0;" : "+l"(acc) : "l"(a), "l"(b))
#define ADD2(d, a, b) \
    asm("add.rn.f32x2 %0, %1, %2;" : "=l"(d) : "l"(a), "l"(b))
#define DUP2(d, a) \
    asm("mov.b64 %0, {%1, %1};" : "=l"(d) : "f"(a))
#define PACK2(d, a, b) \
    asm("mov.b64 %0, {%1, %2};" : "=l"(d) : "f"(a), "f"(b))
#define UNPACK2(a, b, d) \
    asm("mov.b64 {%0, %1}, %2;" : "=f"(a), "=f"(b) : "l"(d))

__device__ __forceinline__ float tanh_ap(float x) {
    float y;
    asm("tanh.approx.f32 %0, %1;" : "=f"(y) : "f"(x));
    return y;
}
__device__ __forceinline__ float sigm_t(float x) {
    return fmaf(0.5f, tanh_ap(0.5f * x), 0.5f);
}

// ---------------------------------------------------------------------------
// Kernel 1: vocab-table GEMM.
//   table[v, dir*256+g] = sum_k emb[v,k]*W_ih[g,k] + (b_ih[g]+b_hh[g])
//   Tile 128x64, 256 thr, 8x4 microtile, f32x2 packed on N.
// ---------------------------------------------------------------------------
#define TKc 50
#define LDAa 132   // A smem row stride (floats), 16B aligned
#define LDBb 68    // B smem row stride

__global__ __launch_bounds__(256)
void vocab_gemm(const float* __restrict__ emb,
                const float* __restrict__ Wih_f,
                const float* __restrict__ bih_f,
                const float* __restrict__ bhh_f,
                const float* __restrict__ Wih_b,
                const float* __restrict__ bih_b,
                const float* __restrict__ bhh_b)
{
    const int tid = threadIdx.x;
    const int tx = tid & 15;           // N microtile (4 cols = 2 f32x2)
    const int ty = tid >> 4;           // M microtile (8 rows)
    const int rb = blockIdx.x * 128;   // vocab row base
    const int cb = blockIdx.y * 64;    // col base (0..448)
    const int dir = cb >> 8;
    const int gb  = cb & 255;

    const float* __restrict__ W  = dir ? Wih_b : Wih_f;
    const float* __restrict__ bi = dir ? bih_b : bih_f;
    const float* __restrict__ bh = dir ? bhh_b : bhh_f;

    __shared__ __align__(16) float As[TKc * LDAa];
    __shared__ __align__(16) float Bs[TKc * LDBb];
    __shared__ float bias_s[64];

    if (tid < 64) bias_s[tid] = bi[gb + tid] + bh[gb + tid];

    unsigned long long acc[8][2];
#pragma unroll
    for (int i = 0; i < 8; i++) { acc[i][0] = 0ull; acc[i][1] = 0ull; }

    const float2* __restrict__ emb2 = (const float2*)emb;
    const float2* __restrict__ W2   = (const float2*)W;

    for (int kc = 0; kc < Ez; kc += TKc) {
        if (kc) __syncthreads();
        // Stage A: 128 rows x 25 float2
        for (int p = tid; p < 128 * 25; p += 256) {
            int q = p % 25;
            int m = p / 25;
            int row = rb + m; if (row >= Vz) row = Vz - 1;
            float2 va = emb2[(size_t)row * 50 + (kc >> 1) + q];
            As[(2 * q)     * LDAa + m] = va.x;
            As[(2 * q + 1) * LDAa + m] = va.y;
        }
        // Stage B: 64 rows x 25 float2
        for (int p = tid; p < 64 * 25; p += 256) {
            int q = p % 25;
            int m = p / 25;
            float2 vb = W2[(size_t)(gb + m) * 50 + (kc >> 1) + q];
            Bs[(2 * q)     * LDBb + m] = vb.x;
            Bs[(2 * q + 1) * LDBb + m] = vb.y;
        }
        __syncthreads();

#pragma unroll 5
        for (int k = 0; k < TKc; k++) {
            float4 aA = *(const float4*)(As + k * LDAa + ty * 8);
            float4 aB = *(const float4*)(As + k * LDAa + ty * 8 + 4);
            ulonglong2 b2 = *(const ulonglong2*)(Bs + k * LDBb + tx * 4);
            unsigned long long ad[8];
            DUP2(ad[0], aA.x); DUP2(ad[1], aA.y);
            DUP2(ad[2], aA.z); DUP2(ad[3], aA.w);
            DUP2(ad[4], aB.x); DUP2(ad[5], aB.y);
            DUP2(ad[6], aB.z); DUP2(ad[7], aB.w);
#pragma unroll
            for (int i = 0; i < 8; i++) {
                FMA2(acc[i][0], ad[i], b2.x);
                FMA2(acc[i][1], ad[i], b2.y);
            }
        }
    }

    float4 bb = *(const float4*)(bias_s + tx * 4);
#pragma unroll
    for (int i = 0; i < 8; i++) {
        float c0, c1, c2, c3;
        UNPACK2(c0, c1, acc[i][0]);
        UNPACK2(c2, c3, acc[i][1]);
        float4 o = make_float4(c0 + bb.x, c1 + bb.y, c2 + bb.z, c3 + bb.w);
        int row = rb + ty * 8 + i;      // < VP always
        *(float4*)&g_table[(size_t)row * NC + cb + tx * 4] = o;
    }
}

// ---------------------------------------------------------------------------
// Kernel 2: LSTM recurrence. 4 chains (batch rows) per block, 128 blocks.
// Thread (warp w, lane l): gate slot g=l>>3 (i,f,g,o), cell e = w*8 + (l&7).
// Computes gate row j = g*64+e for all 4 chains; 4x4 shfl transpose puts the
// 4 gate values of (chain=g, cell=e) in this lane; update is warp-local.
// Single __syncthreads per step with double-buffered h.
// ---------------------------------------------------------------------------
#define HS 68   // padded h row stride (floats); 272B = 16B-aligned

__global__ __launch_bounds__(256)
void lstm_rec(const int* __restrict__ x,
              const float* __restrict__ Whh_f,
              const float* __restrict__ Whh_b)
{
    const int tid = threadIdx.x;
    const int lane = tid & 31;
    const int w    = tid >> 5;
    const int g    = lane >> 3;          // gate slot 0..3
    const int i8   = lane & 7;
    const int e    = w * 8 + i8;         // cell 0..63
    const int j    = g * 64 + e;         // gate row

    const int bg  = blockIdx.x;          // batch group (4 rows)
    const int dir = blockIdx.y;
    const float* __restrict__ W = dir ? Whh_b : Whh_f;

    __shared__ int toks[4][Sz];
    __shared__ __align__(16) float h_sh[2][4 * HS];

    for (int p = tid; p < 4 * Sz; p += 256) {
        int r = p >> 9, t = p & 511;
        toks[r][t] = x[(bg * 4 + r) * Sz + t];
    }
    // zero h buffer 0 (4*68 = 272 entries)
    for (int p = tid; p < 4 * HS; p += 256) h_sh[0][p] = 0.0f;

    // gate-row weights, f32x2 packed over k
    ulonglong2 wv[16];
    const ulonglong2* Wp = (const ulonglong2*)(W + j * Hz);
#pragma unroll
    for (int m = 0; m < 16; m++) wv[m] = Wp[m];

    float c = 0.0f, h_own = 0.0f;
    const float* __restrict__ tb = g_table + dir * Gz + j;

    __syncthreads();

    int t = dir ? (Sz - 1) : 0;
    const int dt = dir ? -1 : 1;

    float xc[4];
#pragma unroll
    for (int r = 0; r < 4; r++) xc[r] = tb[(size_t)toks[r][t] * NC];

    int pb = 0;
#pragma unroll 1
    for (int s = 0; s < Sz; s++) {
        int tn = t + dt;
        float xn[4] = {0.f, 0.f, 0.f, 0.f};
        if (s < Sz - 1) {
#pragma unroll
            for (int r = 0; r < 4; r++) xn[r] = tb[(size_t)toks[r][tn] * NC];
        }

        // matvec: v[r] = xc[r] + dot(W_hh[j], h[r])
        unsigned long long accA[4], accB[4];
#pragma unroll
        for (int r = 0; r < 4; r++) {
            PACK2(accA[r], xc[r], 0.0f);
            accB[r] = 0ull;
        }
#pragma unroll
        for (int m = 0; m < 16; m++) {
#pragma unroll
            for (int r = 0; r < 4; r++) {
                ulonglong2 hv = *(const ulonglong2*)(h_sh[pb] + r * HS + 4 * m);
                FMA2(accA[r], wv[m].x, hv.x);
                FMA2(accB[r], wv[m].y, hv.y);
            }
        }
        float v[4];
#pragma unroll
        for (int r = 0; r < 4; r++) {
            unsigned long long acs;
            ADD2(acs, accA[r], accB[r]);
            float lo, hi;
            UNPACK2(lo, hi, acs);
            v[r] = lo + hi;
        }

        // 4x4 lane-group transpose: after this, tq[q] = gate-q value of
        // chain (this lane's g) at cell e.
        float tq[4];
        tq[g] = v[g];
#pragma unroll
        for (int p = 1; p < 4; p++) {
            int send_idx = (g + p) & 3;
            int recv_idx = (g - p) & 3;
            int src = (recv_idx << 3) | i8;
            tq[recv_idx] = __shfl_sync(0xFFFFFFFFu, v[send_idx], src);
        }

        // update cell (chain g, cell e)
        {
            float gi = sigm_t(tq[0]);
            float gf = sigm_t(tq[1]);
            float gg = tanh_ap(tq[2]);
            float go = sigm_t(tq[3]);
            c = gf * c + gi * gg;
            h_own = go * tanh_ap(c);
            h_sh[pb ^ 1][g * HS + e] = h_own;
        }
        __syncthreads();

        pb ^= 1;
#pragma unroll
        for (int r = 0; r < 4; r++) xc[r] = xn[r];
        t = tn;
    }

    // lane (g, e) holds final h of chain g
    g_hfin[(size_t)(dir * Bz + bg * 4 + g) * Hz + e] = h_own;
}

// ---------------------------------------------------------------------------
// Kernel 3: final FC + sigmoid
// ---------------------------------------------------------------------------
__global__ void final_fc(const float* __restrict__ fcw,
                         const float* __restrict__ fcb,
                         float* __restrict__ out)
{
    int b = threadIdx.x;
    if (b >= Bz) return;
    float acc = fcb[0];
    const float* hf = g_hfin + b * Hz;
    const float* hb = g_hfin + Bz * Hz + b * Hz;
#pragma unroll
    for (int u = 0; u < Hz; u++) {
        acc = fmaf(hf[u], fcw[u], acc);
        acc = fmaf(hb[u], fcw[Hz + u], acc);
    }
    out[b] = __fdividef(1.0f, 1.0f + __expf(-acc));
}

// ---------------------------------------------------------------------------
extern "C" void kernel_launch(void* const* d_in, const int* in_sizes, int n_in,
                              void* d_out, int out_size)
{
    const int*   x     = (const int*)  d_in[0];
    const float* emb   = (const float*)d_in[1];
    const float* Wih_f = (const float*)d_in[2];
    const float* Whh_f = (const float*)d_in[3];
    const float* bih_f = (const float*)d_in[4];
    const float* bhh_f = (const float*)d_in[5];
    const float* Wih_b = (const float*)d_in[6];
    const float* Whh_b = (const float*)d_in[7];
    const float* bih_b = (const float*)d_in[8];
    const float* bhh_b = (const float*)d_in[9];
    const float* fcw   = (const float*)d_in[10];
    const float* fcb   = (const float*)d_in[11];
    float* out = (float*)d_out;

    dim3 g1(VP / 128, NC / 64);   // 391 x 8
    vocab_gemm<<<g1, 256>>>(emb, Wih_f, bih_f, bhh_f, Wih_b, bih_b, bhh_b);

    dim3 g2(Bz / 4, 2);           // 64 x 2 = 128 blocks, one wave
    lstm_rec<<<g2, 256>>>(x, Whh_f, Whh_b);

    final_fc<<<1, 256>>>(fcw, fcb, out);
}